// round 8
// baseline (speedup 1.0000x reference)
#include <cuda_runtime.h>
#include <cuda_bf16.h>
#include <math.h>
#include <stdint.h>

#define BATCH 1024
#define DIN   256
#define HID   512
#define KOUT  32
#define NOUT  (DIN * KOUT)  // 8192

typedef __nv_bfloat16 bf16;

// Scratch (allocation-free rule -> __device__ globals)
__device__ bf16 g_xhi[BATCH * DIN],  g_xlo[BATCH * DIN];
__device__ bf16 g_w0hi[HID * DIN],   g_w0lo[HID * DIN];
__device__ bf16 g_w1hi[HID * HID],   g_w1lo[HID * HID];
__device__ bf16 g_w2hi[HID * HID],   g_w2lo[HID * HID];
__device__ bf16 g_h0hi[BATCH * HID], g_h0lo[BATCH * HID];
__device__ bf16 g_h1hi[BATCH * HID], g_h1lo[BATCH * HID];
__device__ bf16 g_h2hi[BATCH * HID], g_h2lo[BATCH * HID];
__device__ bf16 g_whi[NOUT * HID],   g_wlo[NOUT * HID];

// ---------------------------------------------------------------------------
// PTX helpers (sm_80-baseline: ldmatrix / mma.sync / cp.async — tcgen05 is
// rejected by this toolchain's compute_103 stage)
// ---------------------------------------------------------------------------
__device__ __forceinline__ uint32_t smem_u32(const void* p) {
    uint32_t a;
    asm("{ .reg .u64 t; cvta.to.shared.u64 t, %1; cvt.u32.u64 %0, t; }" : "=r"(a) : "l"(p));
    return a;
}
__device__ __forceinline__ void ldm_x4(uint32_t* r, uint32_t addr) {
    asm volatile("ldmatrix.sync.aligned.m8n8.x4.shared.b16 {%0,%1,%2,%3}, [%4];"
                 : "=r"(r[0]), "=r"(r[1]), "=r"(r[2]), "=r"(r[3]) : "r"(addr));
}
__device__ __forceinline__ void mma_bf16(float* d, const uint32_t* a, const uint32_t* b) {
    asm volatile("mma.sync.aligned.m16n8k16.row.col.f32.bf16.bf16.f32 "
                 "{%0,%1,%2,%3}, {%4,%5,%6,%7}, {%8,%9}, {%0,%1,%2,%3};"
                 : "+f"(d[0]), "+f"(d[1]), "+f"(d[2]), "+f"(d[3])
                 : "r"(a[0]), "r"(a[1]), "r"(a[2]), "r"(a[3]), "r"(b[0]), "r"(b[1]));
}
__device__ __forceinline__ void cp16(uint32_t dst, const void* src) {
    asm volatile("cp.async.cg.shared.global [%0], [%1], 16;" :: "r"(dst), "l"(src) : "memory");
}
__device__ __forceinline__ void cp_commit() {
    asm volatile("cp.async.commit_group;" ::: "memory");
}
template<int N> __device__ __forceinline__ void cp_wait() {
    asm volatile("cp.async.wait_group %0;" :: "n"(N) : "memory");
}
__device__ __forceinline__ void split2(float v, bf16& h, bf16& l) {
    h = __float2bfloat16(v);
    l = __float2bfloat16(v - __bfloat162float(h));
}
// min of (k % 255) over k in [a, a+32)
__device__ __forceinline__ int minmod255(int a) {
    return ((a + 31) / 255 > a / 255) ? 0 : (a % 255);
}

// ---------------------------------------------------------------------------
// Merged prep: split Wout, x, W0, W1, W2 into bf16 hi/lo, masks folded in.
// Region by global thread id (4 floats per thread). 4992 CTAs.
// ---------------------------------------------------------------------------
#define T_WOUT (NOUT * HID / 4)            // 1048576
#define T_X    (T_WOUT + BATCH * DIN / 4)  // +65536
#define T_W0   (T_X + HID * DIN / 4)       // +32768
#define T_W1   (T_W0 + HID * HID / 4)      // +65536
#define T_W2   (T_W1 + HID * HID / 4)      // +65536

__global__ void __launch_bounds__(256) prep_kernel(
    const float* __restrict__ Wout, const float* __restrict__ x,
    const float* __restrict__ W0,   const float* __restrict__ W1,
    const float* __restrict__ W2)
{
    int t = blockIdx.x * 256 + threadIdx.x;
    if (t < T_WOUT) {
        int base = t * 4;
        int n = base >> 9, k0 = base & 511;
        int od = (n >> 5) - 1;
        float4 w4 = *(const float4*)(Wout + base);
        float wv[4] = {w4.x, w4.y, w4.z, w4.w};
        bf16 h[4], l[4];
        #pragma unroll
        for (int q = 0; q < 4; q++) {
            float v = (od >= ((k0 + q) % 255)) ? wv[q] : 0.0f;
            split2(v, h[q], l[q]);
        }
        *(uint2*)(g_whi + base) = *(uint2*)h;
        *(uint2*)(g_wlo + base) = *(uint2*)l;
        return;
    }
    const float* src; bf16 *hi, *lo;
    int mode, ksh, base;
    if (t < T_X)       { src = x;  hi = g_xhi;  lo = g_xlo;  mode = -1; ksh = 8; base = (t - T_WOUT) * 4; }
    else if (t < T_W0) { src = W0; hi = g_w0hi; lo = g_w0lo; mode = 0;  ksh = 8; base = (t - T_X) * 4; }
    else if (t < T_W1) { src = W1; hi = g_w1hi; lo = g_w1lo; mode = 1;  ksh = 9; base = (t - T_W0) * 4; }
    else               { src = W2; hi = g_w2hi; lo = g_w2lo; mode = 1;  ksh = 9; base = (t - T_W1) * 4; }

    float4 v4 = *(const float4*)(src + base);
    float vv[4] = {v4.x, v4.y, v4.z, v4.w};
    int n = base >> ksh;
    int k0 = base & ((1 << ksh) - 1);
    int nd = n % 255;
    bf16 h[4], l[4];
    #pragma unroll
    for (int q = 0; q < 4; q++) {
        float v = vv[q];
        int k = k0 + q;
        if (mode == 0 && !(nd >= k)) v = 0.0f;
        if (mode == 1 && !(nd >= (k % 255))) v = 0.0f;
        split2(v, h[q], l[q]);
    }
    *(uint2*)(hi + base) = *(uint2*)h;
    *(uint2*)(lo + base) = *(uint2*)l;
}

// ---------------------------------------------------------------------------
// Small-layer HMMA kernel: C = relu(A @ W^T + b), split epilogue -> Chi/Clo.
// Tile 32m x 64n, BK=32, 128 threads. 3-stage cp.async, chunk-skip.
// (Unchanged from R7.)
// ---------------------------------------------------------------------------
template<int K, int MODE>
__global__ void __launch_bounds__(128) layer_kernel(
    const bf16* __restrict__ Ahi, const bf16* __restrict__ Alo,
    const bf16* __restrict__ Whi, const bf16* __restrict__ Wlo,
    const float* __restrict__ bias,
    bf16* __restrict__ Chi, bf16* __restrict__ Clo)
{
    constexpr int NC = K / 32;
    constexpr int S = 3;
    constexpr uint32_t STG = 12288;
    extern __shared__ bf16 smL[];
    const int tid = threadIdx.x, lane = tid & 31, wn = tid >> 5;
    const int bm = blockIdx.y * 32;
    const int bn = ((int)gridDim.x - 1 - (int)blockIdx.x) * 64;
    const uint32_t sb = smem_u32(smL);

    const int md = (bn / 255 == (bn + 63) / 255) ? ((bn + 63) % 255) : 254;

    int act[NC]; int na = 0;
    #pragma unroll
    for (int kc = 0; kc < NC; kc++) {
        int mm = (MODE == 0) ? (32 * kc) : minmod255(32 * kc);
        if (md >= mm) act[na++] = kc;
    }

    auto load_stage = [&](int s, int kc) {
        uint32_t stg = sb + (uint32_t)s * STG;
        {
            int r = tid >> 2, c = tid & 3;
            uint32_t dsw = (uint32_t)(r * 64 + ((c ^ ((r >> 1) & 3)) << 4));
            size_t asrc = (size_t)(bm + r) * K + kc * 32 + c * 8;
            cp16(stg + dsw,         Ahi + asrc);
            cp16(stg + 2048u + dsw, Alo + asrc);
        }
        #pragma unroll
        for (int i = 0; i < 2; i++) {
            int idx = tid + i * 128;
            int r = idx >> 2, c = idx & 3;
            uint32_t dsw = (uint32_t)(r * 64 + ((c ^ ((r >> 1) & 3)) << 4));
            size_t wsrc = (size_t)(bn + r) * K + kc * 32 + c * 8;
            cp16(stg + 4096u + dsw, Whi + wsrc);
            cp16(stg + 8192u + dsw, Wlo + wsrc);
        }
    };

    int raby[2], swa[2];
    #pragma unroll
    for (int mi = 0; mi < 2; mi++) {
        int r = mi * 16 + (lane & 15);
        raby[mi] = r * 64;
        swa[mi] = (r >> 1) & 3;
    }
    const int hiA = lane >> 4;
    const int nloc = wn * 16 + (((lane >> 3) >> 1) << 3) + (lane & 7);
    const int rbby = nloc * 64, swb = (nloc >> 1) & 3, cbB = (lane >> 3) & 1;

    float acc[2][2][4];
    #pragma unroll
    for (int a = 0; a < 2; a++)
        #pragma unroll
        for (int bq = 0; bq < 2; bq++)
            #pragma unroll
            for (int q = 0; q < 4; q++) acc[a][bq][q] = 0.0f;

    #pragma unroll
    for (int s = 0; s < S - 1; s++) { if (s < na) load_stage(s, act[s]); cp_commit(); }

    #pragma unroll 1
    for (int ii = 0; ii < na; ii++) {
        cp_wait<S - 2>();
        __syncthreads();
        int ld = ii + S - 1;
        if (ld < na) load_stage(ld % S, act[ld]);
        cp_commit();

        uint32_t stg = sb + (uint32_t)(ii % S) * STG;
        #pragma unroll
        for (int k16 = 0; k16 < 2; k16++) {
            uint32_t a0[2][4], a1[2][4];
            #pragma unroll
            for (int mi = 0; mi < 2; mi++) {
                uint32_t off = (uint32_t)(raby[mi] + ((((k16 << 1) | hiA) ^ swa[mi]) << 4));
                ldm_x4(a0[mi], stg + off);
                ldm_x4(a1[mi], stg + 2048u + off);
            }
            uint32_t boff = (uint32_t)(rbby + ((((k16 << 1) | cbB) ^ swb) << 4));
            uint32_t bh[4];
            ldm_x4(bh, stg + 4096u + boff);
            #pragma unroll
            for (int mi = 0; mi < 2; mi++) {
                mma_bf16(acc[mi][0], a0[mi], &bh[0]);
                mma_bf16(acc[mi][1], a0[mi], &bh[2]);
                mma_bf16(acc[mi][0], a1[mi], &bh[0]);
                mma_bf16(acc[mi][1], a1[mi], &bh[2]);
            }
            uint32_t bl[4];
            ldm_x4(bl, stg + 8192u + boff);
            #pragma unroll
            for (int mi = 0; mi < 2; mi++) {
                mma_bf16(acc[mi][0], a0[mi], &bl[0]);
                mma_bf16(acc[mi][1], a0[mi], &bl[2]);
            }
        }
    }
    cp_wait<0>();

    const int r0 = bm + (lane >> 2);
    const int c0 = bn + wn * 16 + (lane & 3) * 2;
    #pragma unroll
    for (int mi = 0; mi < 2; mi++) {
        #pragma unroll
        for (int nj = 0; nj < 2; nj++) {
            int c = c0 + nj * 8;
            float b0 = bias[c], b1 = bias[c + 1];
            float v00 = fmaxf(acc[mi][nj][0] + b0, 0.0f);
            float v01 = fmaxf(acc[mi][nj][1] + b1, 0.0f);
            float v10 = fmaxf(acc[mi][nj][2] + b0, 0.0f);
            float v11 = fmaxf(acc[mi][nj][3] + b1, 0.0f);
            bf16 h0, l0, h1, l1;
            split2(v00, h0, l0); split2(v01, h1, l1);
            size_t o0 = (size_t)(r0 + mi * 16) * HID + c;
            *(__nv_bfloat162*)(Chi + o0) = __halves2bfloat162(h0, h1);
            *(__nv_bfloat162*)(Clo + o0) = __halves2bfloat162(l0, l1);
            split2(v10, h0, l0); split2(v11, h1, l1);
            size_t o1 = (size_t)(r0 + mi * 16 + 8) * HID + c;
            *(__nv_bfloat162*)(Chi + o1) = __halves2bfloat162(h0, h1);
            *(__nv_bfloat162*)(Clo + o1) = __halves2bfloat162(l0, l1);
        }
    }
}

// ---------------------------------------------------------------------------
// Big HMMA GEMM: theta[1024,8192] = h2 @ Wout^T + bout (3-term split).
// Tile 128m x 64n, BK=32, 256 threads (8 warps = 4m x 2n, warp 32x32).
// 3-stage pipeline (24KB/stage -> 3 CTAs/SM), finer chunk-skip (T=bn/32+1),
// heavy tiles first. Grid (128, 8) = 1024 CTAs.
// ---------------------------------------------------------------------------
__global__ void __launch_bounds__(256) gemm_mma_kernel(
    const bf16* __restrict__ Ahi, const bf16* __restrict__ Alo,
    const bf16* __restrict__ Whi, const bf16* __restrict__ Wlo,
    const float* __restrict__ bias, float* __restrict__ C)
{
    constexpr int NC = HID / 32;   // 16
    constexpr int S = 3;
    constexpr uint32_t STG = 24576;
    extern __shared__ bf16 smd[];
    const int tid = threadIdx.x, lane = tid & 31, wrp = tid >> 5;
    const int wm = wrp >> 1, wn = wrp & 1;
    const int bm = blockIdx.y * 128;
    const int bn = ((int)gridDim.x - 1 - (int)blockIdx.x) * 64;
    const uint32_t sb = smem_u32(smd);

    // W tile nonzero iff min(k%255 over chunk) <= max od in tile = bn/32+1
    const int T = (bn >> 5) + 1;
    int act[NC]; int na = 0;
    #pragma unroll
    for (int kc = 0; kc < NC; kc++)
        if (minmod255(32 * kc) <= T) act[na++] = kc;

    auto load_stage = [&](int s, int kc) {
        uint32_t stg = sb + (uint32_t)s * STG;
        #pragma unroll
        for (int i = 0; i < 2; i++) {  // A: 128 rows x 32 cols, hi+lo
            int idx = tid + i * 256;
            int r = idx >> 2, c = idx & 3;
            uint32_t dsw = (uint32_t)(r * 64 + ((c ^ ((r >> 1) & 3)) << 4));
            size_t asrc = (size_t)(bm + r) * HID + kc * 32 + c * 8;
            cp16(stg + dsw,         Ahi + asrc);
            cp16(stg + 8192u + dsw, Alo + asrc);
        }
        {   // W: 64 rows x 32 cols, hi+lo
            int r = tid >> 2, c = tid & 3;
            uint32_t dsw = (uint32_t)(r * 64 + ((c ^ ((r >> 1) & 3)) << 4));
            size_t wsrc = (size_t)(bn + r) * HID + kc * 32 + c * 8;
            cp16(stg + 16384u + dsw, Whi + wsrc);
            cp16(stg + 20480u + dsw, Wlo + wsrc);
        }
    };

    int raby[2], swa[2];
    #pragma unroll
    for (int mi = 0; mi < 2; mi++) {
        int r = wm * 32 + mi * 16 + (lane & 15);
        raby[mi] = r * 64;
        swa[mi] = (r >> 1) & 3;
    }
    const int hiA = lane >> 4;
    int rbby[2], swb[2];
    #pragma unroll
    for (int p = 0; p < 2; p++) {
        int n = wn * 32 + p * 16 + (((lane >> 3) >> 1) << 3) + (lane & 7);
        rbby[p] = n * 64;
        swb[p] = (n >> 1) & 3;
    }
    const int cbB = (lane >> 3) & 1;

    float acc[2][4][4];
    #pragma unroll
    for (int a = 0; a < 2; a++)
        #pragma unroll
        for (int bq = 0; bq < 4; bq++)
            #pragma unroll
            for (int q = 0; q < 4; q++) acc[a][bq][q] = 0.0f;

    #pragma unroll
    for (int s = 0; s < S - 1; s++) { if (s < na) load_stage(s, act[s]); cp_commit(); }

    #pragma unroll 1
    for (int ii = 0; ii < na; ii++) {
        cp_wait<S - 2>();
        __syncthreads();
        int ld = ii + S - 1;
        if (ld < na) load_stage(ld % S, act[ld]);
        cp_commit();

        uint32_t stg = sb + (uint32_t)(ii % S) * STG;
        #pragma unroll
        for (int k16 = 0; k16 < 2; k16++) {
            uint32_t a0[2][4], a1[2][4];
            #pragma unroll
            for (int mi = 0; mi < 2; mi++) {
                uint32_t off = (uint32_t)(raby[mi] + ((((k16 << 1) | hiA) ^ swa[mi]) << 4));
                ldm_x4(a0[mi], stg + off);
                ldm_x4(a1[mi], stg + 8192u + off);
            }
            #pragma unroll
            for (int p = 0; p < 2; p++) {
                uint32_t boff = (uint32_t)(rbby[p] + ((((k16 << 1) | cbB) ^ swb[p]) << 4));
                uint32_t bh[4];
                ldm_x4(bh, stg + 16384u + boff);
                #pragma unroll
                for (int mi = 0; mi < 2; mi++) {
                    mma_bf16(acc[mi][p * 2 + 0], a0[mi], &bh[0]);
                    mma_bf16(acc[mi][p * 2 + 1], a0[mi], &bh[2]);
                    mma_bf16(acc[mi][p * 2 + 0], a1[mi], &bh[0]);
                    mma_bf16(acc[mi][p * 2 + 1], a1[mi], &bh[2]);
                }
                uint32_t bl[4];
                ldm_x4(bl, stg + 20480u + boff);
                #pragma unroll
                for (int mi = 0; mi < 2; mi++) {
                    mma_bf16(acc[mi][p * 2 + 0], a0[mi], &bl[0]);
                    mma_bf16(acc[mi][p * 2 + 1], a0[mi], &bl[2]);
                }
            }
        }
    }
    cp_wait<0>();

    const int r0 = bm + wm * 32 + (lane >> 2);
    const int cbase = bn + wn * 32 + (lane & 3) * 2;
    #pragma unroll
    for (int mi = 0; mi < 2; mi++) {
        #pragma unroll
        for (int nj = 0; nj < 4; nj++) {
            int col = cbase + nj * 8;
            float b0 = bias[col], b1 = bias[col + 1];
            float2 v0 = {acc[mi][nj][0] + b0, acc[mi][nj][1] + b1};
            float2 v1 = {acc[mi][nj][2] + b0, acc[mi][nj][3] + b1};
            *(float2*)(C + (size_t)(r0 + mi * 16) * NOUT + col)     = v0;
            *(float2*)(C + (size_t)(r0 + mi * 16 + 8) * NOUT + col) = v1;
        }
    }
}

// ---------------------------------------------------------------------------
// Fused log_px + forward chain. 16 lanes/batch, 2 batches/warp. (Unchanged.)
// ---------------------------------------------------------------------------
__global__ void __launch_bounds__(128) chain_kernel(
    const float* __restrict__ x, const float* __restrict__ theta,
    const float* __restrict__ ulpa, float* __restrict__ out)
{
    __shared__ float s_lpa[255 * 4];
    for (int d = threadIdx.x; d < 255; d += 128) {
        float u0 = ulpa[d * 4 + 0], u1 = ulpa[d * 4 + 1];
        float u2 = ulpa[d * 4 + 2], u3 = ulpa[d * 4 + 3];
        float m = fmaxf(fmaxf(u0, u1), fmaxf(u2, u3));
        float s = expf(u0 - m) + expf(u1 - m) + expf(u2 - m) + expf(u3 - m);
        float lse = m + logf(s);
        s_lpa[d * 4 + 0] = u0 - lse;
        s_lpa[d * 4 + 1] = u1 - lse;
        s_lpa[d * 4 + 2] = u2 - lse;
        s_lpa[d * 4 + 3] = u3 - lse;
    }
    __syncthreads();

    const int lane = threadIdx.x & 31;
    const int wid  = threadIdx.x >> 5;
    const int half = lane >> 4;
    const int l    = lane & 15;
    const int i    = l >> 2, j = l & 3;
    const int b    = (blockIdx.x * 4 + wid) * 2 + half;

    const unsigned FULL = 0xffffffffu;
    const float NL = -0.91893853320467274178f;

    const float* th = theta + (size_t)b * NOUT;
    const float* xb = x + (size_t)b * DIN;

    float carry;
    {
        float mu = __ldg(th + l), ls = __ldg(th + 16 + l);
        float xd = __ldg(xb);
        float sd = __expf(ls) + 0.01f;
        float z = __fdividef(xd - mu, sd);
        float lp = fmaf(-0.5f * z, z, NL) - __logf(sd);
        float v = lp + s_lpa[j];
        carry = __shfl_sync(FULL, v, half * 16 + j);
    }
    float mu = __ldg(th + 32 + l), ls = __ldg(th + 48 + l);
    float xd = __ldg(xb + 1);
    #pragma unroll 1
    for (int d = 1; d < 255; d++) {
        float nmu = __ldg(th + (d + 1) * 32 + l);
        float nls = __ldg(th + (d + 1) * 32 + 16 + l);
        float nxd = __ldg(xb + d + 1);
        float sd = __expf(ls) + 0.01f;
        float z = __fdividef(xd - mu, sd);
        float lp = fmaf(-0.5f * z, z, NL) - __logf(sd);
        float ci = __shfl_sync(FULL, carry, half * 16 + i);
        float tv = ci + lp + s_lpa[d * 4 + j];
        float m = fmaxf(tv, __shfl_xor_sync(FULL, tv, 4));
        m = fmaxf(m, __shfl_xor_sync(FULL, m, 8));
        float s = __expf(tv - m);
        s += __shfl_xor_sync(FULL, s, 4);
        s += __shfl_xor_sync(FULL, s, 8);
        carry = m + __logf(s);
        mu = nmu; ls = nls; xd = nxd;
    }
    {
        float sd = __expf(ls) + 0.01f;
        float z = __fdividef(xd - mu, sd);
        float lp = fmaf(-0.5f * z, z, NL) - __logf(sd);
        float ci = __shfl_sync(FULL, carry, half * 16 + i);
        float tv = (j == 0) ? (ci + lp) : -1e30f;
        float m = fmaxf(tv, __shfl_xor_sync(FULL, tv, 1));
        m = fmaxf(m, __shfl_xor_sync(FULL, m, 2));
        m = fmaxf(m, __shfl_xor_sync(FULL, m, 4));
        m = fmaxf(m, __shfl_xor_sync(FULL, m, 8));
        float s = __expf(tv - m);
        s += __shfl_xor_sync(FULL, s, 1);
        s += __shfl_xor_sync(FULL, s, 2);
        s += __shfl_xor_sync(FULL, s, 4);
        s += __shfl_xor_sync(FULL, s, 8);
        if (l == 0) out[b] = m + __logf(s);
    }
}

// ---------------------------------------------------------------------------
// kernel_launch
// ---------------------------------------------------------------------------
extern "C" void kernel_launch(void* const* d_in, const int* in_sizes, int n_in,
                              void* d_out, int out_size)
{
    const float* x    = (const float*)d_in[0];
    const float* W0   = (const float*)d_in[1];
    const float* b0   = (const float*)d_in[2];
    const float* W1   = (const float*)d_in[3];
    const float* b1   = (const float*)d_in[4];
    const float* W2   = (const float*)d_in[5];
    const float* b2   = (const float*)d_in[6];
    const float* Wout = (const float*)d_in[7];
    const float* bout = (const float*)d_in[8];
    const float* ulpa = (const float*)d_in[9];

    float* out   = (float*)d_out;
    float* theta = out + BATCH;

    bf16 *xhi, *xlo, *w0hi, *w0lo, *w1hi, *w1lo, *w2hi, *w2lo;
    bf16 *h0hi, *h0lo, *h1hi, *h1lo, *h2hi, *h2lo, *whi, *wlo;
    cudaGetSymbolAddress((void**)&xhi, g_xhi);   cudaGetSymbolAddress((void**)&xlo, g_xlo);
    cudaGetSymbolAddress((void**)&w0hi, g_w0hi); cudaGetSymbolAddress((void**)&w0lo, g_w0lo);
    cudaGetSymbolAddress((void**)&w1hi, g_w1hi); cudaGetSymbolAddress((void**)&w1lo, g_w1lo);
    cudaGetSymbolAddress((void**)&w2hi, g_w2hi); cudaGetSymbolAddress((void**)&w2lo, g_w2lo);
    cudaGetSymbolAddress((void**)&h0hi, g_h0hi); cudaGetSymbolAddress((void**)&h0lo, g_h0lo);
    cudaGetSymbolAddress((void**)&h1hi, g_h1hi); cudaGetSymbolAddress((void**)&h1lo, g_h1lo);
    cudaGetSymbolAddress((void**)&h2hi, g_h2hi); cudaGetSymbolAddress((void**)&h2lo, g_h2lo);
    cudaGetSymbolAddress((void**)&whi, g_whi);   cudaGetSymbolAddress((void**)&wlo, g_wlo);

    cudaFuncSetAttribute(gemm_mma_kernel,
                         cudaFuncAttributeMaxDynamicSharedMemorySize, 73728);
    cudaFuncSetAttribute(layer_kernel<DIN, 0>,
                         cudaFuncAttributeMaxDynamicSharedMemorySize, 36864);
    cudaFuncSetAttribute(layer_kernel<HID, 1>,
                         cudaFuncAttributeMaxDynamicSharedMemorySize, 36864);

    prep_kernel<<<(T_W2 + 255) / 256, 256>>>(Wout, x, W0, W1, W2);

    layer_kernel<DIN, 0><<<dim3(HID / 64, BATCH / 32), 128, 36864>>>(
        xhi, xlo, w0hi, w0lo, b0, h0hi, h0lo);
    layer_kernel<HID, 1><<<dim3(HID / 64, BATCH / 32), 128, 36864>>>(
        h0hi, h0lo, w1hi, w1lo, b1, h1hi, h1lo);
    layer_kernel<HID, 1><<<dim3(HID / 64, BATCH / 32), 128, 36864>>>(
        h1hi, h1lo, w2hi, w2lo, b2, h2hi, h2lo);

    gemm_mma_kernel<<<dim3(NOUT / 64, BATCH / 128), 256, 73728>>>(
        h2hi, h2lo, whi, wlo, bout, theta);

    chain_kernel<<<BATCH / 8, 128>>>(x, theta, ulpa, out);
}